// round 7
// baseline (speedup 1.0000x reference)
#include <cuda_runtime.h>
#include <stdint.h>

#define TOKENS 16384
#define DIM    4096
#define NE     64
#define BM     64
#define NSTEP  256         // k16 steps
#define NTHR   256

// W in B-fragment order with k-permutation: fragment for kstep j, lane t=lane&3
// holds W cols j*16 + 4t .. 4t+3 (mapped to mma kappa slots 2t,2t+1,8+2t,8+2t+1).
// layout: [kstep j 0..255][nblk 0..7][lane 0..31] -> uint4{b0h,b1h,b0l,b1l}
__device__ __align__(16) uint4 g_wfrag[256 * 8 * 32];

// fp32 -> (bf16 hi, bf16 lo); packed bf16x2 (f0 -> low half, f1 -> high half)
__device__ __forceinline__ void cvt_pair(float f0, float f1, uint32_t& h, uint32_t& l) {
    asm("cvt.rn.bf16x2.f32 %0, %1, %2;" : "=r"(h) : "f"(f1), "f"(f0));
    float hf0 = __uint_as_float(h << 16);
    float hf1 = __uint_as_float(h & 0xffff0000u);
    float r0 = f0 - hf0;
    float r1 = f1 - hf1;
    asm("cvt.rn.bf16x2.f32 %0, %1, %2;" : "=r"(l) : "f"(r1), "f"(r0));
}

__device__ __forceinline__ void mma16816(float c[4], const uint32_t a[4],
                                         uint32_t b0, uint32_t b1) {
    asm volatile(
        "mma.sync.aligned.m16n8k16.row.col.f32.bf16.bf16.f32 "
        "{%0,%1,%2,%3}, {%4,%5,%6,%7}, {%8,%9}, {%0,%1,%2,%3};"
        : "+f"(c[0]), "+f"(c[1]), "+f"(c[2]), "+f"(c[3])
        : "r"(a[0]), "r"(a[1]), "r"(a[2]), "r"(a[3]), "r"(b0), "r"(b1));
}

// ---------------- prep: W fp32 -> bf16 hi/lo, permuted-k fragment order ----------------
__global__ void prep_w(const float* __restrict__ W) {
    int idx = blockIdx.x * 256 + threadIdx.x;      // 0..65535
    int j    = idx >> 8;                           // kstep 0..255
    int lane = idx & 31;
    int nb   = (idx >> 5) & 7;
    int n = nb * 8 + (lane >> 2);
    int k = j * 16 + (lane & 3) * 4;               // 4 consecutive cols
    float4 v = *reinterpret_cast<const float4*>(W + (size_t)n * DIM + k);
    uint32_t h0, l0, h1, l1;
    cvt_pair(v.x, v.y, h0, l0);   // kappa slots 2t, 2t+1
    cvt_pair(v.z, v.w, h1, l1);   // kappa slots 8+2t, 8+2t+1
    g_wfrag[idx] = make_uint4(h0, h1, l0, l1);
}

// ---------------- main fused kernel: pipelined, no k-split ----------------
__global__ __launch_bounds__(NTHR, 2)
void topk_gate_hmma5(const float* __restrict__ x,
                     float* __restrict__ out_logits, float* __restrict__ out_scores,
                     float* __restrict__ out_loss)
{
    __shared__ float slog[BM][NE + 1];
    __shared__ float s_s1[BM], s_s2[BM];
    __shared__ int   s_i1[BM], s_i2[BM];

    const int tid  = threadIdx.x;
    const int lane = tid & 31;
    const int wid  = tid >> 5;          // 0..7
    const int pm   = wid >> 1;          // m-group 0..3 (16 rows each)
    const int wn   = wid & 1;           // n-half 0..1 (32 cols each)
    const size_t m_base = (size_t)blockIdx.x * BM;

    const float* xg  = x + m_base * DIM;
    const float* pA0 = xg + (size_t)(pm * 16 + (lane >> 2)) * DIM + (lane & 3) * 4;
    const float* pA1 = pA0 + 8 * DIM;
    const uint4* wp  = g_wfrag + (size_t)(wn * 4) * 32 + lane;  // kstep s at +s*256

    float acc[4][4];
    #pragma unroll
    for (int nt = 0; nt < 4; nt++)
        #pragma unroll
        for (int q = 0; q < 4; q++) acc[nt][q] = 0.f;

    // pipeline rings: A distance-2 (ring 4), B distance-1 (ring 2)
    float4 Ab[4][2];
    uint4  Bb[2][4];

    Ab[0][0] = *reinterpret_cast<const float4*>(pA0);
    Ab[0][1] = *reinterpret_cast<const float4*>(pA1);
    Ab[1][0] = *reinterpret_cast<const float4*>(pA0 + 16);
    Ab[1][1] = *reinterpret_cast<const float4*>(pA1 + 16);
    #pragma unroll
    for (int nt = 0; nt < 4; nt++) Bb[0][nt] = wp[nt * 32];

    for (int s0 = 0; s0 < NSTEP; s0 += 4) {
        #pragma unroll
        for (int j = 0; j < 4; j++) {
            const int s = s0 + j;
            // ---- prefetch: A for s+2, B for s+1 (clamped; tail re-reads step 255) ----
            int sa = s + 2; sa = (sa < 255) ? sa : 255;
            int sb = s + 1; sb = (sb < 255) ? sb : 255;
            Ab[(j + 2) & 3][0] = *reinterpret_cast<const float4*>(pA0 + (size_t)sa * 16);
            Ab[(j + 2) & 3][1] = *reinterpret_cast<const float4*>(pA1 + (size_t)sa * 16);
            {
                const uint4* wq = wp + (size_t)sb * 256;
                #pragma unroll
                for (int nt = 0; nt < 4; nt++) Bb[(j + 1) & 1][nt] = wq[nt * 32];
            }

            // ---- compute step s ----
            const float4 v0 = Ab[j & 3][0];
            const float4 v1 = Ab[j & 3][1];
            uint32_t ah[4], al[4];
            cvt_pair(v0.x, v0.y, ah[0], al[0]);
            cvt_pair(v1.x, v1.y, ah[1], al[1]);
            cvt_pair(v0.z, v0.w, ah[2], al[2]);
            cvt_pair(v1.z, v1.w, ah[3], al[3]);

            #pragma unroll
            for (int nt = 0; nt < 4; nt++) {
                const uint4 q = Bb[j & 1][nt];
                mma16816(acc[nt], ah, q.x, q.y);  // hi*hi
                mma16816(acc[nt], ah, q.z, q.w);  // hi*lo
                mma16816(acc[nt], al, q.x, q.y);  // lo*hi
            }
        }
    }

    // ---- write logits tile (each warp owns m16 x n32, full K: no reduction) ----
    {
        const int gr = lane >> 2;
        const int gc = (lane & 3) * 2;
        const int r0 = pm * 16 + gr;
        #pragma unroll
        for (int nt = 0; nt < 4; nt++) {
            const int cc = wn * 32 + nt * 8 + gc;
            slog[r0][cc]         = acc[nt][0];
            slog[r0][cc + 1]     = acc[nt][1];
            slog[r0 + 8][cc]     = acc[nt][2];
            slog[r0 + 8][cc + 1] = acc[nt][3];
        }
    }
    __syncthreads();

    if (tid < BM) {
        const float* r = &slog[tid][0];
        float m1 = -3.402823466e38f, m2 = -3.402823466e38f;
        int i1 = 0, i2 = 0;
        #pragma unroll
        for (int e = 0; e < NE; e++) {
            float v = r[e];
            if (v > m1)      { m2 = m1; i2 = i1; m1 = v; i1 = e; }
            else if (v > m2) { m2 = v;  i2 = e; }
        }
        float sum = 0.f;
        #pragma unroll
        for (int e = 0; e < NE; e++) sum += expf(r[e] - m1);
        float lz = m1 + logf(sum);
        out_loss[m_base + tid] = lz * lz;

        float dd = expf(m2 - m1);
        float s1 = 1.f / (1.f + dd);
        s_s1[tid] = s1;
        s_s2[tid] = dd * s1;
        s_i1[tid] = i1;
        s_i2[tid] = i2;
    }
    __syncthreads();

    float* lg = out_logits + m_base * NE;
    float* sc = out_scores + m_base * NE;
    #pragma unroll
    for (int pass = 0; pass < (BM * NE) / NTHR; pass++) {
        int idx = pass * NTHR + tid;
        int t = idx >> 6;
        int e = idx & 63;
        lg[idx] = slog[t][e];
        float sv = (e == s_i1[t]) ? s_s1[t] : ((e == s_i2[t]) ? s_s2[t] : 0.f);
        sc[idx] = sv;
    }
}

extern "C" void kernel_launch(void* const* d_in, const int* in_sizes, int n_in,
                              void* d_out, int out_size)
{
    const float* x = (const float*)d_in[0];
    const float* W = (const float*)d_in[1];
    float* out    = (float*)d_out;
    float* logits = out;
    float* scores = out + (size_t)TOKENS * NE;
    float* loss   = out + (size_t)2 * TOKENS * NE;

    prep_w<<<256, 256>>>(W);
    topk_gate_hmma5<<<TOKENS / BM, NTHR>>>(x, logits, scores, loss);
}

// round 8
// speedup vs baseline: 1.1999x; 1.1999x over previous
#include <cuda_runtime.h>
#include <stdint.h>

#define TOKENS 16384
#define DIM    4096
#define NE     64
#define BM     64
#define NTHR   256

// W in B-fragment order with k-permutation: fragment for kstep j, lane t=lane&3
// holds W cols j*16 + 4t .. 4t+3 (mapped to mma kappa slots 2t,2t+1,8+2t,8+2t+1).
// layout: [kstep j 0..255][nblk 0..7][lane 0..31] -> uint4{b0h,b1h,b0l,b1l}
__device__ __align__(16) uint4 g_wfrag[256 * 8 * 32];

// smem layout (bytes)
#define RED_BYTES  32768                    // 4 slots x 2048 floats
#define SLOG_OFF   RED_BYTES                // 64 x 65 fp32 = 16640
#define S1_OFF     (RED_BYTES + 16640)
#define S2_OFF     (S1_OFF + 256)
#define I1_OFF     (S2_OFF + 256)
#define I2_OFF     (I1_OFF + 256)
#define SMEM_TOTAL (I2_OFF + 256)           // 50432

// fp32 -> (bf16 hi, bf16 lo); packed bf16x2 (f0 -> low half, f1 -> high half)
__device__ __forceinline__ void cvt_pair(float f0, float f1, uint32_t& h, uint32_t& l) {
    asm("cvt.rn.bf16x2.f32 %0, %1, %2;" : "=r"(h) : "f"(f1), "f"(f0));
    float hf0 = __uint_as_float(h << 16);
    float hf1 = __uint_as_float(h & 0xffff0000u);
    float r0 = f0 - hf0;
    float r1 = f1 - hf1;
    asm("cvt.rn.bf16x2.f32 %0, %1, %2;" : "=r"(l) : "f"(r1), "f"(r0));
}

__device__ __forceinline__ void mma16816(float c[4], const uint32_t a[4],
                                         uint32_t b0, uint32_t b1) {
    asm volatile(
        "mma.sync.aligned.m16n8k16.row.col.f32.bf16.bf16.f32 "
        "{%0,%1,%2,%3}, {%4,%5,%6,%7}, {%8,%9}, {%0,%1,%2,%3};"
        : "+f"(c[0]), "+f"(c[1]), "+f"(c[2]), "+f"(c[3])
        : "r"(a[0]), "r"(a[1]), "r"(a[2]), "r"(a[3]), "r"(b0), "r"(b1));
}

// ---------------- prep: W fp32 -> bf16 hi/lo, permuted-k fragment order ----------------
__global__ void prep_w(const float* __restrict__ W) {
    int idx = blockIdx.x * 256 + threadIdx.x;      // 0..65535
    int j    = idx >> 8;                           // kstep 0..255
    int lane = idx & 31;
    int nb   = (idx >> 5) & 7;
    int n = nb * 8 + (lane >> 2);
    int k = j * 16 + (lane & 3) * 4;               // 4 consecutive cols
    float4 v = *reinterpret_cast<const float4*>(W + (size_t)n * DIM + k);
    uint32_t h0, l0, h1, l1;
    cvt_pair(v.x, v.y, h0, l0);   // kappa slots 2t, 2t+1
    cvt_pair(v.z, v.w, h1, l1);   // kappa slots 8+2t, 8+2t+1
    g_wfrag[idx] = make_uint4(h0, h1, l0, l1);
}

// ---------------- main fused kernel: warp tile m32 x n64, k-split 4 ----------------
__global__ __launch_bounds__(NTHR, 2)
void topk_gate_hmma6(const float* __restrict__ x,
                     float* __restrict__ out_logits, float* __restrict__ out_scores,
                     float* __restrict__ out_loss)
{
    extern __shared__ char smem[];
    float* red  = reinterpret_cast<float*>(smem);            // [4][64][32]
    float* slog = reinterpret_cast<float*>(smem + SLOG_OFF); // [64][65]
    float* s_s1 = reinterpret_cast<float*>(smem + S1_OFF);
    float* s_s2 = reinterpret_cast<float*>(smem + S2_OFF);
    int*   s_i1 = reinterpret_cast<int*>(smem + I1_OFF);
    int*   s_i2 = reinterpret_cast<int*>(smem + I2_OFF);

    const int tid  = threadIdx.x;
    const int lane = tid & 31;
    const int wid  = tid >> 5;          // 0..7
    const int mh   = wid >> 2;          // m-half 0..1 (32 rows)
    const int ks   = wid & 3;           // k-slice 0..3 (64 ksteps each)
    const size_t m_base = (size_t)blockIdx.x * BM;

    const float* xg = x + m_base * DIM;

    // A pointers: rows mh*32 + mg*16 + (lane>>2) + rr*8; cols (lane&3)*4 + ks*1024
    const float* pA[4];
    #pragma unroll
    for (int mg = 0; mg < 2; mg++)
        #pragma unroll
        for (int rr = 0; rr < 2; rr++)
            pA[mg * 2 + rr] = xg
                + (size_t)(mh * 32 + mg * 16 + (lane >> 2) + rr * 8) * DIM
                + (lane & 3) * 4 + ks * 1024;

    // B pointer: kstep j = ks*64 + s -> g_wfrag + j*256 + nt*32 + lane
    const uint4* wp = g_wfrag + (size_t)(ks * 64) * 256 + lane;

    float acc[2][8][4];
    #pragma unroll
    for (int mg = 0; mg < 2; mg++)
        #pragma unroll
        for (int nt = 0; nt < 8; nt++)
            #pragma unroll
            for (int q = 0; q < 4; q++) acc[mg][nt][q] = 0.f;

    #pragma unroll 2
    for (int s = 0; s < 64; ++s, wp += 256) {
        // A fragments for this kstep (one float4 per m-row-group)
        const float4 v0 = *reinterpret_cast<const float4*>(pA[0] + s * 16);
        const float4 v1 = *reinterpret_cast<const float4*>(pA[1] + s * 16);
        const float4 v2 = *reinterpret_cast<const float4*>(pA[2] + s * 16);
        const float4 v3 = *reinterpret_cast<const float4*>(pA[3] + s * 16);

        // B fragments batch 1 (nt 0..3)
        uint4 q0 = wp[0], q1 = wp[32], q2 = wp[64], q3 = wp[96];

        uint32_t ah[2][4], al[2][4];
        cvt_pair(v0.x, v0.y, ah[0][0], al[0][0]);
        cvt_pair(v1.x, v1.y, ah[0][1], al[0][1]);
        cvt_pair(v0.z, v0.w, ah[0][2], al[0][2]);
        cvt_pair(v1.z, v1.w, ah[0][3], al[0][3]);
        cvt_pair(v2.x, v2.y, ah[1][0], al[1][0]);
        cvt_pair(v3.x, v3.y, ah[1][1], al[1][1]);
        cvt_pair(v2.z, v2.w, ah[1][2], al[1][2]);
        cvt_pair(v3.z, v3.w, ah[1][3], al[1][3]);

        #pragma unroll
        for (int mg = 0; mg < 2; mg++) {
            mma16816(acc[mg][0], ah[mg], q0.x, q0.y);
            mma16816(acc[mg][0], ah[mg], q0.z, q0.w);
            mma16816(acc[mg][0], al[mg], q0.x, q0.y);
            mma16816(acc[mg][1], ah[mg], q1.x, q1.y);
            mma16816(acc[mg][1], ah[mg], q1.z, q1.w);
            mma16816(acc[mg][1], al[mg], q1.x, q1.y);
            mma16816(acc[mg][2], ah[mg], q2.x, q2.y);
            mma16816(acc[mg][2], ah[mg], q2.z, q2.w);
            mma16816(acc[mg][2], al[mg], q2.x, q2.y);
            mma16816(acc[mg][3], ah[mg], q3.x, q3.y);
            mma16816(acc[mg][3], ah[mg], q3.z, q3.w);
            mma16816(acc[mg][3], al[mg], q3.x, q3.y);
        }

        // B fragments batch 2 (nt 4..7)
        q0 = wp[128]; q1 = wp[160]; q2 = wp[192]; q3 = wp[224];

        #pragma unroll
        for (int mg = 0; mg < 2; mg++) {
            mma16816(acc[mg][4], ah[mg], q0.x, q0.y);
            mma16816(acc[mg][4], ah[mg], q0.z, q0.w);
            mma16816(acc[mg][4], al[mg], q0.x, q0.y);
            mma16816(acc[mg][5], ah[mg], q1.x, q1.y);
            mma16816(acc[mg][5], ah[mg], q1.z, q1.w);
            mma16816(acc[mg][5], al[mg], q1.x, q1.y);
            mma16816(acc[mg][6], ah[mg], q2.x, q2.y);
            mma16816(acc[mg][6], ah[mg], q2.z, q2.w);
            mma16816(acc[mg][6], al[mg], q2.x, q2.y);
            mma16816(acc[mg][7], ah[mg], q3.x, q3.y);
            mma16816(acc[mg][7], ah[mg], q3.z, q3.w);
            mma16816(acc[mg][7], al[mg], q3.x, q3.y);
        }
    }

    // ---- k-slice tree reduction: [idx][lane] layout, conflict-free ----
    const int slot = mh * 2 + (ks >> 1);
    float* rp = red + slot * 2048;

    if (ks & 1) {   // ks 1,3 dump
        #pragma unroll
        for (int mg = 0; mg < 2; mg++)
            #pragma unroll
            for (int nt = 0; nt < 8; nt++)
                #pragma unroll
                for (int q = 0; q < 4; q++)
                    rp[(mg * 32 + nt * 4 + q) * 32 + lane] = acc[mg][nt][q];
    }
    __syncthreads();
    if (!(ks & 1)) {   // ks 0,2 add
        #pragma unroll
        for (int mg = 0; mg < 2; mg++)
            #pragma unroll
            for (int nt = 0; nt < 8; nt++)
                #pragma unroll
                for (int q = 0; q < 4; q++)
                    acc[mg][nt][q] += rp[(mg * 32 + nt * 4 + q) * 32 + lane];
    }
    __syncthreads();
    if (ks == 2) {  // dump into slot mh*2 (freed)
        float* rp2 = red + (mh * 2) * 2048;
        #pragma unroll
        for (int mg = 0; mg < 2; mg++)
            #pragma unroll
            for (int nt = 0; nt < 8; nt++)
                #pragma unroll
                for (int q = 0; q < 4; q++)
                    rp2[(mg * 32 + nt * 4 + q) * 32 + lane] = acc[mg][nt][q];
    }
    __syncthreads();
    if (ks == 0) {  // final add + write logits tile
        const float* rp2 = red + (mh * 2) * 2048;
        const int gr = lane >> 2;
        const int gc = (lane & 3) * 2;
        #pragma unroll
        for (int mg = 0; mg < 2; mg++) {
            const int r0 = mh * 32 + mg * 16 + gr;
            #pragma unroll
            for (int nt = 0; nt < 8; nt++) {
                float c0 = acc[mg][nt][0] + rp2[(mg * 32 + nt * 4 + 0) * 32 + lane];
                float c1 = acc[mg][nt][1] + rp2[(mg * 32 + nt * 4 + 1) * 32 + lane];
                float c2 = acc[mg][nt][2] + rp2[(mg * 32 + nt * 4 + 2) * 32 + lane];
                float c3 = acc[mg][nt][3] + rp2[(mg * 32 + nt * 4 + 3) * 32 + lane];
                const int cc = nt * 8 + gc;
                slog[r0 * 65 + cc]           = c0;
                slog[r0 * 65 + cc + 1]       = c1;
                slog[(r0 + 8) * 65 + cc]     = c2;
                slog[(r0 + 8) * 65 + cc + 1] = c3;
            }
        }
    }
    __syncthreads();

    if (tid < BM) {
        const float* r = slog + tid * 65;
        float m1 = -3.402823466e38f, m2 = -3.402823466e38f;
        int i1 = 0, i2 = 0;
        #pragma unroll
        for (int e = 0; e < NE; e++) {
            float v = r[e];
            if (v > m1)      { m2 = m1; i2 = i1; m1 = v; i1 = e; }
            else if (v > m2) { m2 = v;  i2 = e; }
        }
        float sum = 0.f;
        #pragma unroll
        for (int e = 0; e < NE; e++) sum += expf(r[e] - m1);
        float lz = m1 + logf(sum);
        out_loss[m_base + tid] = lz * lz;

        float dd = expf(m2 - m1);
        float s1 = 1.f / (1.f + dd);
        s_s1[tid] = s1;
        s_s2[tid] = dd * s1;
        s_i1[tid] = i1;
        s_i2[tid] = i2;
    }
    __syncthreads();

    float* lg = out_logits + m_base * NE;
    float* sc = out_scores + m_base * NE;
    #pragma unroll
    for (int pass = 0; pass < (BM * NE) / NTHR; pass++) {
        int idx = pass * NTHR + tid;
        int t = idx >> 6;
        int e = idx & 63;
        lg[idx] = slog[t * 65 + e];
        float sv = (e == s_i1[t]) ? s_s1[t] : ((e == s_i2[t]) ? s_s2[t] : 0.f);
        sc[idx] = sv;
    }
}

extern "C" void kernel_launch(void* const* d_in, const int* in_sizes, int n_in,
                              void* d_out, int out_size)
{
    const float* x = (const float*)d_in[0];
    const float* W = (const float*)d_in[1];
    float* out    = (float*)d_out;
    float* logits = out;
    float* scores = out + (size_t)TOKENS * NE;
    float* loss   = out + (size_t)2 * TOKENS * NE;

    prep_w<<<256, 256>>>(W);

    cudaFuncSetAttribute(topk_gate_hmma6,
                         cudaFuncAttributeMaxDynamicSharedMemorySize, SMEM_TOTAL);
    topk_gate_hmma6<<<TOKENS / BM, NTHR, SMEM_TOTAL>>>(x, logits, scores, loss);
}

// round 9
// speedup vs baseline: 1.2121x; 1.0102x over previous
#include <cuda_runtime.h>
#include <stdint.h>

#define TOKENS 16384
#define DIM    4096
#define NE     64
#define BM     64
#define NTHR   256

// W in B-fragment order with k-permutation: fragment for kstep j, lane t=lane&3
// holds W cols j*16 + 4t .. 4t+3 (mapped to mma kappa slots 2t,2t+1,8+2t,8+2t+1).
// layout: [kstep j 0..255][nblk 0..7][lane 0..31] -> uint4{b0h,b1h,b0l,b1l}
__device__ __align__(16) uint4 g_wfrag[256 * 8 * 32];

// smem layout (bytes)
#define RED_BYTES  32768                    // 4 slots x 2048 floats
#define SLOG_OFF   RED_BYTES                // 64 x 65 fp32 = 16640
#define S1_OFF     (RED_BYTES + 16640)
#define S2_OFF     (S1_OFF + 256)
#define I1_OFF     (S2_OFF + 256)
#define I2_OFF     (I1_OFF + 256)
#define SMEM_TOTAL (I2_OFF + 256)           // 50432

// fp32 -> (bf16 hi, bf16 lo); packed bf16x2 (f0 -> low half, f1 -> high half)
__device__ __forceinline__ void cvt_pair(float f0, float f1, uint32_t& h, uint32_t& l) {
    asm("cvt.rn.bf16x2.f32 %0, %1, %2;" : "=r"(h) : "f"(f1), "f"(f0));
    float hf0 = __uint_as_float(h << 16);
    float hf1 = __uint_as_float(h & 0xffff0000u);
    float r0 = f0 - hf0;
    float r1 = f1 - hf1;
    asm("cvt.rn.bf16x2.f32 %0, %1, %2;" : "=r"(l) : "f"(r1), "f"(r0));
}

__device__ __forceinline__ void mma16816(float c[4], const uint32_t a[4],
                                         uint32_t b0, uint32_t b1) {
    asm volatile(
        "mma.sync.aligned.m16n8k16.row.col.f32.bf16.bf16.f32 "
        "{%0,%1,%2,%3}, {%4,%5,%6,%7}, {%8,%9}, {%0,%1,%2,%3};"
        : "+f"(c[0]), "+f"(c[1]), "+f"(c[2]), "+f"(c[3])
        : "r"(a[0]), "r"(a[1]), "r"(a[2]), "r"(a[3]), "r"(b0), "r"(b1));
}

// ---------------- prep: W fp32 -> bf16 hi/lo, permuted-k fragment order ----------------
__global__ void prep_w(const float* __restrict__ W) {
    int idx = blockIdx.x * 256 + threadIdx.x;      // 0..65535
    int j    = idx >> 8;                           // kstep 0..255
    int lane = idx & 31;
    int nb   = (idx >> 5) & 7;
    int n = nb * 8 + (lane >> 2);
    int k = j * 16 + (lane & 3) * 4;               // 4 consecutive cols
    float4 v = *reinterpret_cast<const float4*>(W + (size_t)n * DIM + k);
    uint32_t h0, l0, h1, l1;
    cvt_pair(v.x, v.y, h0, l0);   // kappa slots 2t, 2t+1
    cvt_pair(v.z, v.w, h1, l1);   // kappa slots 8+2t, 8+2t+1
    g_wfrag[idx] = make_uint4(h0, h1, l0, l1);
}

// ---------------- main fused kernel: warp tile m32 x n64, k-split 4, MLP-batched ----------------
__global__ __launch_bounds__(NTHR, 2)
void topk_gate_hmma7(const float* __restrict__ x,
                     float* __restrict__ out_logits, float* __restrict__ out_scores,
                     float* __restrict__ out_loss)
{
    extern __shared__ char smem[];
    float* red  = reinterpret_cast<float*>(smem);            // [4][64][32]
    float* slog = reinterpret_cast<float*>(smem + SLOG_OFF); // [64][65]
    float* s_s1 = reinterpret_cast<float*>(smem + S1_OFF);
    float* s_s2 = reinterpret_cast<float*>(smem + S2_OFF);
    int*   s_i1 = reinterpret_cast<int*>(smem + I1_OFF);
    int*   s_i2 = reinterpret_cast<int*>(smem + I2_OFF);

    const int tid  = threadIdx.x;
    const int lane = tid & 31;
    const int wid  = tid >> 5;          // 0..7
    const int mh   = wid >> 2;          // m-half 0..1 (32 rows)
    const int ks   = wid & 3;           // k-slice 0..3 (64 ksteps each)
    const size_t m_base = (size_t)blockIdx.x * BM;

    // A pointers: mg0/mg1 row bases; rr=+8 rows expressed as immediate offset 8*DIM.
    const float* pA0 = x + m_base * DIM
        + (size_t)(mh * 32 + (lane >> 2)) * DIM + (lane & 3) * 4 + ks * 1024;
    const float* pA1 = pA0 + (size_t)16 * DIM;

    // B pointer: kstep j = ks*64 + s -> g_wfrag + j*256 + nt*32 + lane
    const uint4* wp = g_wfrag + (size_t)(ks * 64) * 256 + lane;

    float acc[2][8][4];
    #pragma unroll
    for (int mg = 0; mg < 2; mg++)
        #pragma unroll
        for (int nt = 0; nt < 8; nt++)
            #pragma unroll
            for (int q = 0; q < 4; q++) acc[mg][nt][q] = 0.f;

    #pragma unroll 1
    for (int s = 0; s < 64; ++s, pA0 += 16, pA1 += 16, wp += 256) {
        // ---- batched loads: A (DRAM) first, then B batch1 (L2) ----
        const float4 v0 = *reinterpret_cast<const float4*>(pA0);
        const float4 v1 = *reinterpret_cast<const float4*>(pA0 + 8 * DIM);
        const float4 v2 = *reinterpret_cast<const float4*>(pA1);
        const float4 v3 = *reinterpret_cast<const float4*>(pA1 + 8 * DIM);
        const uint4 q0 = wp[0], q1 = wp[32], q2 = wp[64], q3 = wp[96];

        // ---- cvt mg0 while loads land ----
        uint32_t ah0[4], al0[4];
        cvt_pair(v0.x, v0.y, ah0[0], al0[0]);
        cvt_pair(v1.x, v1.y, ah0[1], al0[1]);
        cvt_pair(v0.z, v0.w, ah0[2], al0[2]);
        cvt_pair(v1.z, v1.w, ah0[3], al0[3]);

        // ---- B batch2 issued early, consumed ~36 mmas later ----
        const uint4 q4 = wp[128], q5 = wp[160], q6 = wp[192], q7 = wp[224];

        // ---- mma mg0 x batch1 ----
        mma16816(acc[0][0], ah0, q0.x, q0.y);
        mma16816(acc[0][0], ah0, q0.z, q0.w);
        mma16816(acc[0][1], ah0, q1.x, q1.y);
        mma16816(acc[0][1], ah0, q1.z, q1.w);
        mma16816(acc[0][2], ah0, q2.x, q2.y);
        mma16816(acc[0][2], ah0, q2.z, q2.w);
        mma16816(acc[0][3], ah0, q3.x, q3.y);
        mma16816(acc[0][3], ah0, q3.z, q3.w);
        mma16816(acc[0][0], al0, q0.x, q0.y);
        mma16816(acc[0][1], al0, q1.x, q1.y);
        mma16816(acc[0][2], al0, q2.x, q2.y);
        mma16816(acc[0][3], al0, q3.x, q3.y);

        // ---- cvt mg1 (A registers die here) ----
        uint32_t ah1[4], al1[4];
        cvt_pair(v2.x, v2.y, ah1[0], al1[0]);
        cvt_pair(v3.x, v3.y, ah1[1], al1[1]);
        cvt_pair(v2.z, v2.w, ah1[2], al1[2]);
        cvt_pair(v3.z, v3.w, ah1[3], al1[3]);

        // ---- mma mg1 x batch1 (batch1 dies) ----
        mma16816(acc[1][0], ah1, q0.x, q0.y);
        mma16816(acc[1][0], ah1, q0.z, q0.w);
        mma16816(acc[1][1], ah1, q1.x, q1.y);
        mma16816(acc[1][1], ah1, q1.z, q1.w);
        mma16816(acc[1][2], ah1, q2.x, q2.y);
        mma16816(acc[1][2], ah1, q2.z, q2.w);
        mma16816(acc[1][3], ah1, q3.x, q3.y);
        mma16816(acc[1][3], ah1, q3.z, q3.w);
        mma16816(acc[1][0], al1, q0.x, q0.y);
        mma16816(acc[1][1], al1, q1.x, q1.y);
        mma16816(acc[1][2], al1, q2.x, q2.y);
        mma16816(acc[1][3], al1, q3.x, q3.y);

        // ---- mma mg0 x batch2 ----
        mma16816(acc[0][4], ah0, q4.x, q4.y);
        mma16816(acc[0][4], ah0, q4.z, q4.w);
        mma16816(acc[0][5], ah0, q5.x, q5.y);
        mma16816(acc[0][5], ah0, q5.z, q5.w);
        mma16816(acc[0][6], ah0, q6.x, q6.y);
        mma16816(acc[0][6], ah0, q6.z, q6.w);
        mma16816(acc[0][7], ah0, q7.x, q7.y);
        mma16816(acc[0][7], ah0, q7.z, q7.w);
        mma16816(acc[0][4], al0, q4.x, q4.y);
        mma16816(acc[0][5], al0, q5.x, q5.y);
        mma16816(acc[0][6], al0, q6.x, q6.y);
        mma16816(acc[0][7], al0, q7.x, q7.y);

        // ---- mma mg1 x batch2 ----
        mma16816(acc[1][4], ah1, q4.x, q4.y);
        mma16816(acc[1][4], ah1, q4.z, q4.w);
        mma16816(acc[1][5], ah1, q5.x, q5.y);
        mma16816(acc[1][5], ah1, q5.z, q5.w);
        mma16816(acc[1][6], ah1, q6.x, q6.y);
        mma16816(acc[1][6], ah1, q6.z, q6.w);
        mma16816(acc[1][7], ah1, q7.x, q7.y);
        mma16816(acc[1][7], ah1, q7.z, q7.w);
        mma16816(acc[1][4], al1, q4.x, q4.y);
        mma16816(acc[1][5], al1, q5.x, q5.y);
        mma16816(acc[1][6], al1, q6.x, q6.y);
        mma16816(acc[1][7], al1, q7.x, q7.y);
    }

    // ---- k-slice tree reduction: [idx][lane] layout, conflict-free ----
    const int slot = mh * 2 + (ks >> 1);
    float* rp = red + slot * 2048;

    if (ks & 1) {   // ks 1,3 dump
        #pragma unroll
        for (int mg = 0; mg < 2; mg++)
            #pragma unroll
            for (int nt = 0; nt < 8; nt++)
                #pragma unroll
                for (int q = 0; q < 4; q++)
                    rp[(mg * 32 + nt * 4 + q) * 32 + lane] = acc[mg][nt][q];
    }
    __syncthreads();
    if (!(ks & 1)) {   // ks 0,2 add
        #pragma unroll
        for (int mg = 0; mg < 2; mg++)
            #pragma unroll
            for (int nt = 0; nt < 8; nt++)
                #pragma unroll
                for (int q = 0; q < 4; q++)
                    acc[mg][nt][q] += rp[(mg * 32 + nt * 4 + q) * 32 + lane];
    }
    __syncthreads();
    if (ks == 2) {  // dump into slot mh*2 (freed)
        float* rp2 = red + (mh * 2) * 2048;
        #pragma unroll
        for (int mg = 0; mg < 2; mg++)
            #pragma unroll
            for (int nt = 0; nt < 8; nt++)
                #pragma unroll
                for (int q = 0; q < 4; q++)
                    rp2[(mg * 32 + nt * 4 + q) * 32 + lane] = acc[mg][nt][q];
    }
    __syncthreads();
    if (ks == 0) {  // final add + write logits tile
        const float* rp2 = red + (mh * 2) * 2048;
        const int gr = lane >> 2;
        const int gc = (lane & 3) * 2;
        #pragma unroll
        for (int mg = 0; mg < 2; mg++) {
            const int r0 = mh * 32 + mg * 16 + gr;
            #pragma unroll
            for (int nt = 0; nt < 8; nt++) {
                float c0 = acc[mg][nt][0] + rp2[(mg * 32 + nt * 4 + 0) * 32 + lane];
                float c1 = acc[mg][nt][1] + rp2[(mg * 32 + nt * 4 + 1) * 32 + lane];
                float c2 = acc[mg][nt][2] + rp2[(mg * 32 + nt * 4 + 2) * 32 + lane];
                float c3 = acc[mg][nt][3] + rp2[(mg * 32 + nt * 4 + 3) * 32 + lane];
                const int cc = nt * 8 + gc;
                slog[r0 * 65 + cc]           = c0;
                slog[r0 * 65 + cc + 1]       = c1;
                slog[(r0 + 8) * 65 + cc]     = c2;
                slog[(r0 + 8) * 65 + cc + 1] = c3;
            }
        }
    }
    __syncthreads();

    if (tid < BM) {
        const float* r = slog + tid * 65;
        float m1 = -3.402823466e38f, m2 = -3.402823466e38f;
        int i1 = 0, i2 = 0;
        #pragma unroll
        for (int e = 0; e < NE; e++) {
            float v = r[e];
            if (v > m1)      { m2 = m1; i2 = i1; m1 = v; i1 = e; }
            else if (v > m2) { m2 = v;  i2 = e; }
        }
        float sum = 0.f;
        #pragma unroll
        for (int e = 0; e < NE; e++) sum += expf(r[e] - m1);
        float lz = m1 + logf(sum);
        out_loss[m_base + tid] = lz * lz;

        float dd = expf(m2 - m1);
        float s1 = 1.f / (1.f + dd);
        s_s1[tid] = s1;
        s_s2[tid] = dd * s1;
        s_i1[tid] = i1;
        s_i2[tid] = i2;
    }
    __syncthreads();

    float* lg = out_logits + m_base * NE;
    float* sc = out_scores + m_base * NE;
    #pragma unroll
    for (int pass = 0; pass < (BM * NE) / NTHR; pass++) {
        int idx = pass * NTHR + tid;
        int t = idx >> 6;
        int e = idx & 63;
        lg[idx] = slog[t * 65 + e];
        float sv = (e == s_i1[t]) ? s_s1[t] : ((e == s_i2[t]) ? s_s2[t] : 0.f);
        sc[idx] = sv;
    }
}

extern "C" void kernel_launch(void* const* d_in, const int* in_sizes, int n_in,
                              void* d_out, int out_size)
{
    const float* x = (const float*)d_in[0];
    const float* W = (const float*)d_in[1];
    float* out    = (float*)d_out;
    float* logits = out;
    float* scores = out + (size_t)TOKENS * NE;
    float* loss   = out + (size_t)2 * TOKENS * NE;

    prep_w<<<256, 256>>>(W);

    cudaFuncSetAttribute(topk_gate_hmma7,
                         cudaFuncAttributeMaxDynamicSharedMemorySize, SMEM_TOTAL);
    topk_gate_hmma7<<<TOKENS / BM, NTHR, SMEM_TOTAL>>>(x, logits, scores, loss);
}

// round 10
// speedup vs baseline: 1.2327x; 1.0170x over previous
#include <cuda_runtime.h>
#include <stdint.h>

#define TOKENS 16384
#define DIM    4096
#define NE     64
#define BM     64
#define NTHR   256

// W in B-fragment order with k-permutation: fragment for kstep j, lane t=lane&3
// holds W cols j*16 + 4t .. 4t+3 (mapped to mma kappa slots 2t,2t+1,8+2t,8+2t+1).
// layout: [kstep j 0..255][nblk 0..7][lane 0..31] -> uint4{b0h,b1h,b0l,b1l}
__device__ __align__(16) uint4 g_wfrag[256 * 8 * 32];

// smem layout (bytes)
#define RED_BYTES  32768                    // 4 slots x 2048 floats
#define SLOG_OFF   RED_BYTES                // 64 x 65 fp32 = 16640
#define S1_OFF     (RED_BYTES + 16640)
#define S2_OFF     (S1_OFF + 256)
#define I1_OFF     (S2_OFF + 256)
#define I2_OFF     (I1_OFF + 256)
#define SMEM_TOTAL (I2_OFF + 256)           // 50432

// fp32 -> (bf16 hi, bf16 lo); packed bf16x2 (f0 -> low half, f1 -> high half)
__device__ __forceinline__ void cvt_pair(float f0, float f1, uint32_t& h, uint32_t& l) {
    asm("cvt.rn.bf16x2.f32 %0, %1, %2;" : "=r"(h) : "f"(f1), "f"(f0));
    float hf0 = __uint_as_float(h << 16);
    float hf1 = __uint_as_float(h & 0xffff0000u);
    float r0 = f0 - hf0;
    float r1 = f1 - hf1;
    asm("cvt.rn.bf16x2.f32 %0, %1, %2;" : "=r"(l) : "f"(r1), "f"(r0));
}

__device__ __forceinline__ void mma16816(float c[4], const uint32_t a[4],
                                         uint32_t b0, uint32_t b1) {
    asm volatile(
        "mma.sync.aligned.m16n8k16.row.col.f32.bf16.bf16.f32 "
        "{%0,%1,%2,%3}, {%4,%5,%6,%7}, {%8,%9}, {%0,%1,%2,%3};"
        : "+f"(c[0]), "+f"(c[1]), "+f"(c[2]), "+f"(c[3])
        : "r"(a[0]), "r"(a[1]), "r"(a[2]), "r"(a[3]), "r"(b0), "r"(b1));
}

// ---------------- prep: W fp32 -> bf16 hi/lo, permuted-k fragment order ----------------
__global__ void prep_w(const float* __restrict__ W) {
    int idx = blockIdx.x * 256 + threadIdx.x;      // 0..65535
    int j    = idx >> 8;                           // kstep 0..255
    int lane = idx & 31;
    int nb   = (idx >> 5) & 7;
    int n = nb * 8 + (lane >> 2);
    int k = j * 16 + (lane & 3) * 4;               // 4 consecutive cols
    float4 v = *reinterpret_cast<const float4*>(W + (size_t)n * DIM + k);
    uint32_t h0, l0, h1, l1;
    cvt_pair(v.x, v.y, h0, l0);   // kappa slots 2t, 2t+1
    cvt_pair(v.z, v.w, h1, l1);   // kappa slots 8+2t, 8+2t+1
    g_wfrag[idx] = make_uint4(h0, h1, l0, l1);
}

// ---------------- main fused kernel: m32 x n64, k-split 4, distance-8 mma schedule ----------------
__global__ __launch_bounds__(NTHR, 2)
void topk_gate_hmma8(const float* __restrict__ x,
                     float* __restrict__ out_logits, float* __restrict__ out_scores,
                     float* __restrict__ out_loss)
{
    extern __shared__ char smem[];
    float* red  = reinterpret_cast<float*>(smem);            // [4][64][32]
    float* slog = reinterpret_cast<float*>(smem + SLOG_OFF); // [64][65]
    float* s_s1 = reinterpret_cast<float*>(smem + S1_OFF);
    float* s_s2 = reinterpret_cast<float*>(smem + S2_OFF);
    int*   s_i1 = reinterpret_cast<int*>(smem + I1_OFF);
    int*   s_i2 = reinterpret_cast<int*>(smem + I2_OFF);

    const int tid  = threadIdx.x;
    const int lane = tid & 31;
    const int wid  = tid >> 5;          // 0..7
    const int mh   = wid >> 2;          // m-half 0..1 (32 rows)
    const int ks   = wid & 3;           // k-slice 0..3 (64 ksteps each)
    const size_t m_base = (size_t)blockIdx.x * BM;

    const float* pA0 = x + m_base * DIM
        + (size_t)(mh * 32 + (lane >> 2)) * DIM + (lane & 3) * 4 + ks * 1024;
    const float* pA1 = pA0 + (size_t)16 * DIM;

    const uint4* wp = g_wfrag + (size_t)(ks * 64) * 256 + lane;

    float acc[2][8][4];
    #pragma unroll
    for (int mg = 0; mg < 2; mg++)
        #pragma unroll
        for (int nt = 0; nt < 8; nt++)
            #pragma unroll
            for (int q = 0; q < 4; q++) acc[mg][nt][q] = 0.f;

    #pragma unroll 1
    for (int s = 0; s < 64; ++s, pA0 += 16, pA1 += 16, wp += 256) {
        // ---- batched loads: A (DRAM) first, then B batch1 (L2) ----
        const float4 v0 = *reinterpret_cast<const float4*>(pA0);
        const float4 v1 = *reinterpret_cast<const float4*>(pA0 + 8 * DIM);
        const float4 v2 = *reinterpret_cast<const float4*>(pA1);
        const float4 v3 = *reinterpret_cast<const float4*>(pA1 + 8 * DIM);
        const uint4 q0 = wp[0], q1 = wp[32], q2 = wp[64], q3 = wp[96];

        // ---- cvt both m-groups while loads land ----
        uint32_t ah0[4], al0[4], ah1[4], al1[4];
        cvt_pair(v0.x, v0.y, ah0[0], al0[0]);
        cvt_pair(v1.x, v1.y, ah0[1], al0[1]);
        cvt_pair(v0.z, v0.w, ah0[2], al0[2]);
        cvt_pair(v1.z, v1.w, ah0[3], al0[3]);
        cvt_pair(v2.x, v2.y, ah1[0], al1[0]);
        cvt_pair(v3.x, v3.y, ah1[1], al1[1]);
        cvt_pair(v2.z, v2.w, ah1[2], al1[2]);
        cvt_pair(v3.z, v3.w, ah1[3], al1[3]);

        // ---- B batch2 issued early ----
        const uint4 q4 = wp[128], q5 = wp[160], q6 = wp[192], q7 = wp[224];

        // ==== batch 1 (nt 0..3): term-major, same-acc distance 8 ====
        // hi*hi
        mma16816(acc[0][0], ah0, q0.x, q0.y);
        mma16816(acc[0][1], ah0, q1.x, q1.y);
        mma16816(acc[0][2], ah0, q2.x, q2.y);
        mma16816(acc[0][3], ah0, q3.x, q3.y);
        mma16816(acc[1][0], ah1, q0.x, q0.y);
        mma16816(acc[1][1], ah1, q1.x, q1.y);
        mma16816(acc[1][2], ah1, q2.x, q2.y);
        mma16816(acc[1][3], ah1, q3.x, q3.y);
        // hi*lo
        mma16816(acc[0][0], ah0, q0.z, q0.w);
        mma16816(acc[0][1], ah0, q1.z, q1.w);
        mma16816(acc[0][2], ah0, q2.z, q2.w);
        mma16816(acc[0][3], ah0, q3.z, q3.w);
        mma16816(acc[1][0], ah1, q0.z, q0.w);
        mma16816(acc[1][1], ah1, q1.z, q1.w);
        mma16816(acc[1][2], ah1, q2.z, q2.w);
        mma16816(acc[1][3], ah1, q3.z, q3.w);
        // lo*hi
        mma16816(acc[0][0], al0, q0.x, q0.y);
        mma16816(acc[0][1], al0, q1.x, q1.y);
        mma16816(acc[0][2], al0, q2.x, q2.y);
        mma16816(acc[0][3], al0, q3.x, q3.y);
        mma16816(acc[1][0], al1, q0.x, q0.y);
        mma16816(acc[1][1], al1, q1.x, q1.y);
        mma16816(acc[1][2], al1, q2.x, q2.y);
        mma16816(acc[1][3], al1, q3.x, q3.y);

        // ==== batch 2 (nt 4..7): term-major, same-acc distance 8 ====
        // hi*hi
        mma16816(acc[0][4], ah0, q4.x, q4.y);
        mma16816(acc[0][5], ah0, q5.x, q5.y);
        mma16816(acc[0][6], ah0, q6.x, q6.y);
        mma16816(acc[0][7], ah0, q7.x, q7.y);
        mma16816(acc[1][4], ah1, q4.x, q4.y);
        mma16816(acc[1][5], ah1, q5.x, q5.y);
        mma16816(acc[1][6], ah1, q6.x, q6.y);
        mma16816(acc[1][7], ah1, q7.x, q7.y);
        // hi*lo
        mma16816(acc[0][4], ah0, q4.z, q4.w);
        mma16816(acc[0][5], ah0, q5.z, q5.w);
        mma16816(acc[0][6], ah0, q6.z, q6.w);
        mma16816(acc[0][7], ah0, q7.z, q7.w);
        mma16816(acc[1][4], ah1, q4.z, q4.w);
        mma16816(acc[1][5], ah1, q5.z, q5.w);
        mma16816(acc[1][6], ah1, q6.z, q6.w);
        mma16816(acc[1][7], ah1, q7.z, q7.w);
        // lo*hi
        mma16816(acc[0][4], al0, q4.x, q4.y);
        mma16816(acc[0][5], al0, q5.x, q5.y);
        mma16816(acc[0][6], al0, q6.x, q6.y);
        mma16816(acc[0][7], al0, q7.x, q7.y);
        mma16816(acc[1][4], al1, q4.x, q4.y);
        mma16816(acc[1][5], al1, q5.x, q5.y);
        mma16816(acc[1][6], al1, q6.x, q6.y);
        mma16816(acc[1][7], al1, q7.x, q7.y);
    }

    // ---- k-slice tree reduction: [idx][lane] layout, conflict-free ----
    const int slot = mh * 2 + (ks >> 1);
    float* rp = red + slot * 2048;

    if (ks & 1) {   // ks 1,3 dump
        #pragma unroll
        for (int mg = 0; mg < 2; mg++)
            #pragma unroll
            for (int nt = 0; nt < 8; nt++)
                #pragma unroll
                for (int q = 0; q < 4; q++)
                    rp[(mg * 32 + nt * 4 + q) * 32 + lane] = acc[mg][nt][q];
    }
    __syncthreads();
    if (!(ks & 1)) {   // ks 0,2 add
        #pragma unroll
        for (int mg = 0; mg < 2; mg++)
            #pragma unroll
            for (int nt = 0; nt < 8; nt++)
                #pragma unroll
                for (int q = 0; q < 4; q++)
                    acc[mg][nt][q] += rp[(mg * 32 + nt * 4 + q) * 32 + lane];
    }
    __syncthreads();
    if (ks == 2) {  // dump into slot mh*2 (freed)
        float* rp2 = red + (mh * 2) * 2048;
        #pragma unroll
        for (int mg = 0; mg < 2; mg++)
            #pragma unroll
            for (int nt = 0; nt < 8; nt++)
                #pragma unroll
                for (int q = 0; q < 4; q++)
                    rp2[(mg * 32 + nt * 4 + q) * 32 + lane] = acc[mg][nt][q];
    }
    __syncthreads();
    if (ks == 0) {  // final add + write logits tile
        const float* rp2 = red + (mh * 2) * 2048;
        const int gr = lane >> 2;
        const int gc = (lane & 3) * 2;
        #pragma unroll
        for (int mg = 0; mg < 2; mg++) {
            const int r0 = mh * 32 + mg * 16 + gr;
            #pragma unroll
            for (int nt = 0; nt < 8; nt++) {
                float c0 = acc[mg][nt][0] + rp2[(mg * 32 + nt * 4 + 0) * 32 + lane];
                float c1 = acc[mg][nt][1] + rp2[(mg * 32 + nt * 4 + 1) * 32 + lane];
                float c2 = acc[mg][nt][2] + rp2[(mg * 32 + nt * 4 + 2) * 32 + lane];
                float c3 = acc[mg][nt][3] + rp2[(mg * 32 + nt * 4 + 3) * 32 + lane];
                const int cc = nt * 8 + gc;
                slog[r0 * 65 + cc]           = c0;
                slog[r0 * 65 + cc + 1]       = c1;
                slog[(r0 + 8) * 65 + cc]     = c2;
                slog[(r0 + 8) * 65 + cc + 1] = c3;
            }
        }
    }
    __syncthreads();

    if (tid < BM) {
        const float* r = slog + tid * 65;
        float m1 = -3.402823466e38f, m2 = -3.402823466e38f;
        int i1 = 0, i2 = 0;
        #pragma unroll
        for (int e = 0; e < NE; e++) {
            float v = r[e];
            if (v > m1)      { m2 = m1; i2 = i1; m1 = v; i1 = e; }
            else if (v > m2) { m2 = v;  i2 = e; }
        }
        float sum = 0.f;
        #pragma unroll
        for (int e = 0; e < NE; e++) sum += expf(r[e] - m1);
        float lz = m1 + logf(sum);
        out_loss[m_base + tid] = lz * lz;

        float dd = expf(m2 - m1);
        float s1 = 1.f / (1.f + dd);
        s_s1[tid] = s1;
        s_s2[tid] = dd * s1;
        s_i1[tid] = i1;
        s_i2[tid] = i2;
    }
    __syncthreads();

    float* lg = out_logits + m_base * NE;
    float* sc = out_scores + m_base * NE;
    #pragma unroll
    for (int pass = 0; pass < (BM * NE) / NTHR; pass++) {
        int idx = pass * NTHR + tid;
        int t = idx >> 6;
        int e = idx & 63;
        lg[idx] = slog[t * 65 + e];
        float sv = (e == s_i1[t]) ? s_s1[t] : ((e == s_i2[t]) ? s_s2[t] : 0.f);
        sc[idx] = sv;
    }
}

extern "C" void kernel_launch(void* const* d_in, const int* in_sizes, int n_in,
                              void* d_out, int out_size)
{
    const float* x = (const float*)d_in[0];
    const float* W = (const float*)d_in[1];
    float* out    = (float*)d_out;
    float* logits = out;
    float* scores = out + (size_t)TOKENS * NE;
    float* loss   = out + (size_t)2 * TOKENS * NE;

    prep_w<<<256, 256>>>(W);

    cudaFuncSetAttribute(topk_gate_hmma8,
                         cudaFuncAttributeMaxDynamicSharedMemorySize, SMEM_TOTAL);
    topk_gate_hmma8<<<TOKENS / BM, NTHR, SMEM_TOTAL>>>(x, logits, scores, loss);
}

// round 11
// speedup vs baseline: 1.2629x; 1.0246x over previous
#include <cuda_runtime.h>
#include <stdint.h>

#define TOKENS 16384
#define DIM    4096
#define NE     64
#define BM     64
#define NTHR   256

// W in B-fragment order with k-permutation: fragment for kstep j, lane t=lane&3
// holds W cols j*16 + 4t .. 4t+3 (mapped to mma kappa slots 2t,2t+1,8+2t,8+2t+1).
// layout: [kstep j 0..255][nblk 0..7][lane 0..31] -> uint4{b0h,b1h,b0l,b1l}
__device__ __align__(16) uint4 g_wfrag[256 * 8 * 32];

// smem layout (bytes)
#define RED_BYTES  32768                    // 4 slots x 2048 floats
#define SLOG_OFF   RED_BYTES                // 64 x 65 fp32 = 16640
#define S1_OFF     (RED_BYTES + 16640)
#define S2_OFF     (S1_OFF + 256)
#define I1_OFF     (S2_OFF + 256)
#define I2_OFF     (I1_OFF + 256)
#define SMEM_TOTAL (I2_OFF + 256)           // 50432

// fp32 -> (bf16 hi, bf16 lo); packed bf16x2 (f0 -> low half, f1 -> high half)
__device__ __forceinline__ void cvt_pair(float f0, float f1, uint32_t& h, uint32_t& l) {
    asm("cvt.rn.bf16x2.f32 %0, %1, %2;" : "=r"(h) : "f"(f1), "f"(f0));
    float hf0 = __uint_as_float(h << 16);
    float hf1 = __uint_as_float(h & 0xffff0000u);
    float r0 = f0 - hf0;
    float r1 = f1 - hf1;
    asm("cvt.rn.bf16x2.f32 %0, %1, %2;" : "=r"(l) : "f"(r1), "f"(r0));
}

__device__ __forceinline__ void mma16816(float c[4], const uint32_t a[4],
                                         uint32_t b0, uint32_t b1) {
    asm volatile(
        "mma.sync.aligned.m16n8k16.row.col.f32.bf16.bf16.f32 "
        "{%0,%1,%2,%3}, {%4,%5,%6,%7}, {%8,%9}, {%0,%1,%2,%3};"
        : "+f"(c[0]), "+f"(c[1]), "+f"(c[2]), "+f"(c[3])
        : "r"(a[0]), "r"(a[1]), "r"(a[2]), "r"(a[3]), "r"(b0), "r"(b1));
}

// ---------------- prep: W fp32 -> bf16 hi/lo, permuted-k fragment order ----------------
__global__ void prep_w(const float* __restrict__ W) {
    int idx = blockIdx.x * 256 + threadIdx.x;      // 0..65535
    int j    = idx >> 8;                           // kstep 0..255
    int lane = idx & 31;
    int nb   = (idx >> 5) & 7;
    int n = nb * 8 + (lane >> 2);
    int k = j * 16 + (lane & 3) * 4;               // 4 consecutive cols
    float4 v = *reinterpret_cast<const float4*>(W + (size_t)n * DIM + k);
    uint32_t h0, l0, h1, l1;
    cvt_pair(v.x, v.y, h0, l0);   // kappa slots 2t, 2t+1
    cvt_pair(v.z, v.w, h1, l1);   // kappa slots 8+2t, 8+2t+1
    g_wfrag[idx] = make_uint4(h0, h1, l0, l1);
}

// 12 mmas: one m-group x 4 n-tiles, term-major (per-acc distance 4)
#define MMA_GROUP(AC, AH, AL, Q0, Q1, Q2, Q3)          \
    do {                                               \
        mma16816(AC[0], AH, Q0.x, Q0.y);               \
        mma16816(AC[1], AH, Q1.x, Q1.y);               \
        mma16816(AC[2], AH, Q2.x, Q2.y);               \
        mma16816(AC[3], AH, Q3.x, Q3.y);               \
        mma16816(AC[0], AH, Q0.z, Q0.w);               \
        mma16816(AC[1], AH, Q1.z, Q1.w);               \
        mma16816(AC[2], AH, Q2.z, Q2.w);               \
        mma16816(AC[3], AH, Q3.z, Q3.w);               \
        mma16816(AC[0], AL, Q0.x, Q0.y);               \
        mma16816(AC[1], AL, Q1.x, Q1.y);               \
        mma16816(AC[2], AL, Q2.x, Q2.y);               \
        mma16816(AC[3], AL, Q3.x, Q3.y);               \
    } while (0)

// ---------------- main fused kernel: m32 x n64, k-split 4, A prefetched x-iteration ----------------
__global__ __launch_bounds__(NTHR, 2)
void topk_gate_hmma9(const float* __restrict__ x,
                     float* __restrict__ out_logits, float* __restrict__ out_scores,
                     float* __restrict__ out_loss)
{
    extern __shared__ char smem[];
    float* red  = reinterpret_cast<float*>(smem);            // [4][64][32]
    float* slog = reinterpret_cast<float*>(smem + SLOG_OFF); // [64][65]
    float* s_s1 = reinterpret_cast<float*>(smem + S1_OFF);
    float* s_s2 = reinterpret_cast<float*>(smem + S2_OFF);
    int*   s_i1 = reinterpret_cast<int*>(smem + I1_OFF);
    int*   s_i2 = reinterpret_cast<int*>(smem + I2_OFF);

    const int tid  = threadIdx.x;
    const int lane = tid & 31;
    const int wid  = tid >> 5;          // 0..7
    const int mh   = wid >> 2;          // m-half 0..1 (32 rows)
    const int ks   = wid & 3;           // k-slice 0..3 (64 ksteps each)
    const size_t m_base = (size_t)blockIdx.x * BM;

    const float* pA0 = x + m_base * DIM
        + (size_t)(mh * 32 + (lane >> 2)) * DIM + (lane & 3) * 4 + ks * 1024;
    const float* pA1 = pA0 + (size_t)16 * DIM;

    const uint4* wp = g_wfrag + (size_t)(ks * 64) * 256 + lane;

    float acc[2][4][4];       // [mg][nt 0..3 of current batch]... full 8 nt split below
    float acc2[2][4][4];      // nt 4..7
    #pragma unroll
    for (int mg = 0; mg < 2; mg++)
        #pragma unroll
        for (int nt = 0; nt < 4; nt++)
            #pragma unroll
            for (int q = 0; q < 4; q++) { acc[mg][nt][q] = 0.f; acc2[mg][nt][q] = 0.f; }

    // prologue: A(0) resident in vc
    float4 vc0 = *reinterpret_cast<const float4*>(pA0);
    float4 vc1 = *reinterpret_cast<const float4*>(pA0 + 8 * DIM);
    float4 vc2 = *reinterpret_cast<const float4*>(pA1);
    float4 vc3 = *reinterpret_cast<const float4*>(pA1 + 8 * DIM);

    #pragma unroll 1
    for (int s = 0; s < 64; ++s, wp += 256) {
        // ---- B batch1 (needed soonest) ----
        const uint4 q0 = wp[0], q1 = wp[32], q2 = wp[64], q3 = wp[96];

        uint32_t ah[4], al[4];
        // cvt mg0, mma mg0 x batch1
        cvt_pair(vc0.x, vc0.y, ah[0], al[0]);
        cvt_pair(vc1.x, vc1.y, ah[1], al[1]);
        cvt_pair(vc0.z, vc0.w, ah[2], al[2]);
        cvt_pair(vc1.z, vc1.w, ah[3], al[3]);
        MMA_GROUP(acc[0], ah, al, q0, q1, q2, q3);

        // cvt mg1, mma mg1 x batch1
        cvt_pair(vc2.x, vc2.y, ah[0], al[0]);
        cvt_pair(vc3.x, vc3.y, ah[1], al[1]);
        cvt_pair(vc2.z, vc2.w, ah[2], al[2]);
        cvt_pair(vc3.z, vc3.w, ah[3], al[3]);
        MMA_GROUP(acc[1], ah, al, q0, q1, q2, q3);

        // ---- B batch2 ----
        const uint4 q4 = wp[128], q5 = wp[160], q6 = wp[192], q7 = wp[224];

        // re-cvt mg0, mma mg0 x batch2
        cvt_pair(vc0.x, vc0.y, ah[0], al[0]);
        cvt_pair(vc1.x, vc1.y, ah[1], al[1]);
        cvt_pair(vc0.z, vc0.w, ah[2], al[2]);
        cvt_pair(vc1.z, vc1.w, ah[3], al[3]);
        MMA_GROUP(acc2[0], ah, al, q4, q5, q6, q7);

        // re-cvt mg1 (vc dies here)
        cvt_pair(vc2.x, vc2.y, ah[0], al[0]);
        cvt_pair(vc3.x, vc3.y, ah[1], al[1]);
        cvt_pair(vc2.z, vc2.w, ah[2], al[2]);
        cvt_pair(vc3.z, vc3.w, ah[3], al[3]);

        // ---- prefetch A(s+1) into the dead vc regs, ~36 mmas before use ----
        {
            const int sn = (s < 63) ? (s + 1) : 63;
            vc0 = *reinterpret_cast<const float4*>(pA0 + (size_t)sn * 16);
            vc1 = *reinterpret_cast<const float4*>(pA0 + 8 * DIM + (size_t)sn * 16);
            vc2 = *reinterpret_cast<const float4*>(pA1 + (size_t)sn * 16);
            vc3 = *reinterpret_cast<const float4*>(pA1 + 8 * DIM + (size_t)sn * 16);
        }

        // mma mg1 x batch2
        MMA_GROUP(acc2[1], ah, al, q4, q5, q6, q7);
    }

    // ---- k-slice tree reduction: [idx][lane] layout, conflict-free ----
    const int slot = mh * 2 + (ks >> 1);
    float* rp = red + slot * 2048;

    if (ks & 1) {   // ks 1,3 dump
        #pragma unroll
        for (int mg = 0; mg < 2; mg++)
            #pragma unroll
            for (int nt = 0; nt < 4; nt++)
                #pragma unroll
                for (int q = 0; q < 4; q++) {
                    rp[(mg * 32 + nt * 4 + q) * 32 + lane] = acc[mg][nt][q];
                    rp[(mg * 32 + (nt + 4) * 4 + q) * 32 + lane] = acc2[mg][nt][q];
                }
    }
    __syncthreads();
    if (!(ks & 1)) {   // ks 0,2 add
        #pragma unroll
        for (int mg = 0; mg < 2; mg++)
            #pragma unroll
            for (int nt = 0; nt < 4; nt++)
                #pragma unroll
                for (int q = 0; q < 4; q++) {
                    acc[mg][nt][q]  += rp[(mg * 32 + nt * 4 + q) * 32 + lane];
                    acc2[mg][nt][q] += rp[(mg * 32 + (nt + 4) * 4 + q) * 32 + lane];
                }
    }
    __syncthreads();
    if (ks == 2) {  // dump into slot mh*2 (freed)
        float* rp2 = red + (mh * 2) * 2048;
        #pragma unroll
        for (int mg = 0; mg < 2; mg++)
            #pragma unroll
            for (int nt = 0; nt < 4; nt++)
                #pragma unroll
                for (int q = 0; q < 4; q++) {
                    rp2[(mg * 32 + nt * 4 + q) * 32 + lane] = acc[mg][nt][q];
                    rp2[(mg * 32 + (nt + 4) * 4 + q) * 32 + lane] = acc2[mg][nt][q];
                }
    }
    __syncthreads();
    if (ks == 0) {  // final add + write logits tile
        const float* rp2 = red + (mh * 2) * 2048;
        const int gr = lane >> 2;
        const int gc = (lane & 3) * 2;
        #pragma unroll
        for (int mg = 0; mg < 2; mg++) {
            const int r0 = mh * 32 + mg * 16 + gr;
            #pragma unroll
            for (int nt = 0; nt < 8; nt++) {
                float* a = (nt < 4) ? acc[mg][nt] : acc2[mg][nt - 4];
                float c0 = a[0] + rp2[(mg * 32 + nt * 4 + 0) * 32 + lane];
                float c1 = a[1] + rp2[(mg * 32 + nt * 4 + 1) * 32 + lane];
                float c2 = a[2] + rp2[(mg * 32 + nt * 4 + 2) * 32 + lane];
                float c3 = a[3] + rp2[(mg * 32 + nt * 4 + 3) * 32 + lane];
                const int cc = nt * 8 + gc;
                slog[r0 * 65 + cc]           = c0;
                slog[r0 * 65 + cc + 1]       = c1;
                slog[(r0 + 8) * 65 + cc]     = c2;
                slog[(r0 + 8) * 65 + cc + 1] = c3;
            }
        }
    }
    __syncthreads();

    if (tid < BM) {
        const float* r = slog + tid * 65;
        float m1 = -3.402823466e38f, m2 = -3.402823466e38f;
        int i1 = 0, i2 = 0;
        #pragma unroll
        for (int e = 0; e < NE; e++) {
            float v = r[e];
            if (v > m1)      { m2 = m1; i2 = i1; m1 = v; i1 = e; }
            else if (v > m2) { m2 = v;  i2 = e; }
        }
        float sum = 0.f;
        #pragma unroll
        for (int e = 0; e < NE; e++) sum += expf(r[e] - m1);
        float lz = m1 + logf(sum);
        out_loss[m_base + tid] = lz * lz;

        float dd = expf(m2 - m1);
        float s1 = 1.f / (1.f + dd);
        s_s1[tid] = s1;
        s_s2[tid] = dd * s1;
        s_i1[tid] = i1;
        s_i2[tid] = i2;
    }
    __syncthreads();

    float* lg = out_logits + m_base * NE;
    float* sc = out_scores + m_base * NE;
    #pragma unroll
    for (int pass = 0; pass < (BM * NE) / NTHR; pass++) {
        int idx = pass * NTHR + tid;
        int t = idx >> 6;
        int e = idx & 63;
        lg[idx] = slog[t * 65 + e];
        float sv = (e == s_i1[t]) ? s_s1[t] : ((e == s_i2[t]) ? s_s2[t] : 0.f);
        sc[idx] = sv;
    }
}

extern "C" void kernel_launch(void* const* d_in, const int* in_sizes, int n_in,
                              void* d_out, int out_size)
{
    const float* x = (const float*)d_in[0];
    const float* W = (const float*)d_in[1];
    float* out    = (float*)d_out;
    float* logits = out;
    float* scores = out + (size_t)TOKENS * NE;
    float* loss   = out + (size_t)2 * TOKENS * NE;

    prep_w<<<256, 256>>>(W);

    cudaFuncSetAttribute(topk_gate_hmma9,
                         cudaFuncAttributeMaxDynamicSharedMemorySize, SMEM_TOTAL);
    topk_gate_hmma9<<<TOKENS / BM, NTHR, SMEM_TOTAL>>>(x, logits, scores, loss);
}